// round 1
// baseline (speedup 1.0000x reference)
#include <cuda_runtime.h>
#include <math.h>

#define NROWS 8192
#define DDIM  64
#define BM    128
#define BN    128
#define NSPLIT 4
#define JTILES ((NROWS / NSPLIT) / BN)   // 16 j-tiles per CTA

// ---------------------------------------------------------------------------
// Scratch (allocation-free: __device__ globals)
// ---------------------------------------------------------------------------
__device__ float g_z1t[DDIM * NROWS];        // normalized z1, transposed [d][N]
__device__ float g_z2t[DDIM * NROWS];        // normalized z2, transposed [d][N]
__device__ float g_partial[NSPLIT * NROWS];  // per-split partial row sums of exp
__device__ float g_diag[NROWS];              // sim_ii = (z1n_i . z2n_i) / T

// ---------------------------------------------------------------------------
// Kernel 1: normalize rows of both inputs, write transposed; compute diag.
// Input layout (b,d,h,w): addr(n,c) = (n>>12)*DDIM*4096 + (n&4095) + c*4096
// where n = b*4096 + h*64 + w. Consecutive n -> consecutive addresses
// (coalesced), channel stride 4096 floats.
// ---------------------------------------------------------------------------
__global__ void prep_kernel(const float* __restrict__ z1,
                            const float* __restrict__ z2) {
    int n = blockIdx.x * blockDim.x + threadIdx.x;
    if (n >= NROWS) return;
    int base = (n >> 12) * (DDIM * 4096) + (n & 4095);

    float sa = 0.f, sb = 0.f, dt = 0.f;
#pragma unroll 8
    for (int c = 0; c < DDIM; c++) {
        float a = z1[base + c * 4096];
        float b = z2[base + c * 4096];
        sa = fmaf(a, a, sa);
        sb = fmaf(b, b, sb);
        dt = fmaf(a, b, dt);
    }
    float inva = 1.f / fmaxf(sqrtf(sa), 1e-12f);
    float invb = 1.f / fmaxf(sqrtf(sb), 1e-12f);

#pragma unroll 8
    for (int c = 0; c < DDIM; c++) {
        g_z1t[c * NROWS + n] = z1[base + c * 4096] * inva;  // second read hits L1
        g_z2t[c * NROWS + n] = z2[base + c * 4096] * invb;
    }
    g_diag[n] = dt * inva * invb * 10.0f;  // sim_ii (already / T)
}

// ---------------------------------------------------------------------------
// Kernel 2: fused GEMM + streaming sum(exp(sim)).
// CTA: BM=128 rows x (NROWS/NSPLIT) cols in BN=128 tiles, K=64 fully resident.
// Thread (tx,ty): 8x8 micro-tile, rows i0+ty*8+ii, cols j0+tx*8+jj.
// |sim| <= 10 so exp needs no max-shift; partial sums add linearly.
// ---------------------------------------------------------------------------
__global__ void __launch_bounds__(256, 2) gemm_lse_kernel() {
    extern __shared__ float smem[];
    float4* As4 = reinterpret_cast<float4*>(smem);               // [64][32] f4
    float4* Bs4 = reinterpret_cast<float4*>(smem + DDIM * BM);   // [64][32] f4

    const int tid = threadIdx.x;
    const int tx = tid & 15;
    const int ty = tid >> 4;
    const int i0 = blockIdx.x * BM;
    const int jbase = blockIdx.y * (NROWS / NSPLIT);

    // Load A tile [64][128] once (8 float4 per thread, coalesced).
#pragma unroll
    for (int it = 0; it < 8; it++) {
        int e4 = tid + it * 256;
        int k = e4 >> 5;      // 32 float4 per k-row
        int iq = e4 & 31;
        As4[e4] = reinterpret_cast<const float4*>(g_z1t + k * NROWS + i0)[iq];
    }
    __syncthreads();

    float rs[8];
#pragma unroll
    for (int ii = 0; ii < 8; ii++) rs[ii] = 0.f;

    for (int jt = 0; jt < JTILES; jt++) {
        const int j0 = jbase + jt * BN;
        __syncthreads();  // previous iter's Bs readers done
#pragma unroll
        for (int it = 0; it < 8; it++) {
            int e4 = tid + it * 256;
            int k = e4 >> 5;
            int jq = e4 & 31;
            Bs4[e4] = reinterpret_cast<const float4*>(g_z2t + k * NROWS + j0)[jq];
        }
        __syncthreads();

        float acc[8][8];
#pragma unroll
        for (int ii = 0; ii < 8; ii++)
#pragma unroll
            for (int jj = 0; jj < 8; jj++) acc[ii][jj] = 0.f;

#pragma unroll 8
        for (int k = 0; k < DDIM; k++) {
            float4 a0 = As4[k * 32 + ty * 2];
            float4 a1 = As4[k * 32 + ty * 2 + 1];
            float4 b0 = Bs4[k * 32 + tx * 2];
            float4 b1 = Bs4[k * 32 + tx * 2 + 1];
            float av[8] = {a0.x, a0.y, a0.z, a0.w, a1.x, a1.y, a1.z, a1.w};
            float bv[8] = {b0.x, b0.y, b0.z, b0.w, b1.x, b1.y, b1.z, b1.w};
#pragma unroll
            for (int ii = 0; ii < 8; ii++)
#pragma unroll
                for (int jj = 0; jj < 8; jj++)
                    acc[ii][jj] = fmaf(av[ii], bv[jj], acc[ii][jj]);
        }

        // Fused epilogue: sum exp(acc * 10) into per-row accumulators (MUFU
        // pipe, overlaps FMA).
#pragma unroll
        for (int ii = 0; ii < 8; ii++) {
            float s = 0.f;
#pragma unroll
            for (int jj = 0; jj < 8; jj++) s += __expf(acc[ii][jj] * 10.0f);
            rs[ii] += s;
        }
    }

    // Reduce across the 16 tx-lanes sharing each row (stays within half-warp).
#pragma unroll
    for (int off = 8; off > 0; off >>= 1)
#pragma unroll
        for (int ii = 0; ii < 8; ii++)
            rs[ii] += __shfl_xor_sync(0xffffffffu, rs[ii], off);

    if (tx == 0) {
#pragma unroll
        for (int ii = 0; ii < 8; ii++)
            g_partial[blockIdx.y * NROWS + i0 + ty * 8 + ii] = rs[ii];
    }
}

// ---------------------------------------------------------------------------
// Kernel 3: combine split partials, lse - diag, mean.
// ---------------------------------------------------------------------------
__global__ void loss_kernel(float* __restrict__ out) {
    __shared__ float red[256];
    int tid = threadIdx.x;
    float s = 0.f;
    for (int i = tid; i < NROWS; i += 256) {
        float rsum = g_partial[i] + g_partial[NROWS + i] +
                     g_partial[2 * NROWS + i] + g_partial[3 * NROWS + i];
        s += logf(rsum) - g_diag[i];
    }
    red[tid] = s;
    __syncthreads();
    for (int o = 128; o > 0; o >>= 1) {
        if (tid < o) red[tid] += red[tid + o];
        __syncthreads();
    }
    if (tid == 0) out[0] = red[0] * (1.0f / NROWS);
}

// ---------------------------------------------------------------------------
extern "C" void kernel_launch(void* const* d_in, const int* in_sizes, int n_in,
                              void* d_out, int out_size) {
    const float* z1 = (const float*)d_in[0];
    const float* z2 = (const float*)d_in[1];
    float* out = (float*)d_out;

    prep_kernel<<<NROWS / 256, 256>>>(z1, z2);

    const size_t smem_bytes = (size_t)(DDIM * BM + DDIM * BN) * sizeof(float);  // 64 KB
    cudaFuncSetAttribute(gemm_lse_kernel,
                         cudaFuncAttributeMaxDynamicSharedMemorySize,
                         (int)smem_bytes);
    dim3 grid(NROWS / BM, NSPLIT);
    gemm_lse_kernel<<<grid, 256, smem_bytes>>>();

    loss_kernel<<<1, 256>>>(out);
}

// round 4
// speedup vs baseline: 2.5662x; 2.5662x over previous
#include <cuda_runtime.h>
#include <math.h>
#include <stdint.h>

#define NROWS 8192
#define DDIM  64
#define BM    128
#define BN    128
#define NSPLIT 4
#define JTILES ((NROWS / NSPLIT) / BN)   // 16 j-tiles per CTA
#define KPAD  68                          // 64 + 4 pad: bank(m*68+k) = (4m+k)%32

// exp(10*x) = 2^(x * 10/ln2)
#define EXP_SCALE 14.4269504088896f

// ---------------------------------------------------------------------------
// Scratch (allocation-free: __device__ globals)
// ---------------------------------------------------------------------------
__device__ float g_z1r[NROWS * DDIM];        // normalized z1, row-major, tf32-rounded
__device__ float g_z2r[NROWS * DDIM];        // normalized z2, row-major, tf32-rounded
__device__ float g_partial[NSPLIT * NROWS];  // per-split partial row sums of exp
__device__ float g_diag[NROWS];              // sim_ii = (z1n_i . z2n_i) / T  (fp32-exact)

__device__ __forceinline__ float to_tf32(float x) {
    uint32_t r;  // cvt to tf32 requires a .b32 destination
    asm("cvt.rna.tf32.f32 %0, %1;" : "=r"(r) : "f"(x));
    return __uint_as_float(r);
}

__device__ __forceinline__ float ex2(float x) {   // MUFU.EX2, flag-independent
    float r;
    asm("ex2.approx.f32 %0, %1;" : "=f"(r) : "f"(x));
    return r;
}

__device__ __forceinline__ void mma_tf32(float c[4],
                                         uint32_t a0, uint32_t a1, uint32_t a2, uint32_t a3,
                                         uint32_t b0, uint32_t b1) {
    asm volatile(
        "mma.sync.aligned.m16n8k8.row.col.f32.tf32.tf32.f32 "
        "{%0,%1,%2,%3}, {%4,%5,%6,%7}, {%8,%9}, {%0,%1,%2,%3};"
        : "+f"(c[0]), "+f"(c[1]), "+f"(c[2]), "+f"(c[3])
        : "r"(a0), "r"(a1), "r"(a2), "r"(a3), "r"(b0), "r"(b1));
}

// ---------------------------------------------------------------------------
// Kernel 1: normalize rows, write row-major tf32-rounded; diag in fp32.
// 4 threads per row (q = tid&3 handles 16 channels), shfl-reduced.
// Also zero-initializes g_partial (one element per thread, 32768 total).
// ---------------------------------------------------------------------------
__global__ void __launch_bounds__(256) prep_kernel(const float* __restrict__ z1,
                                                   const float* __restrict__ z2) {
    const int tid = threadIdx.x;
    const int gid = blockIdx.x * 256 + tid;
    g_partial[gid] = 0.f;                       // NSPLIT*NROWS == grid*block

    const int r = tid >> 2;
    const int q = tid & 3;
    const int n = blockIdx.x * 64 + r;
    const int base = (n >> 12) * (DDIM * 4096) + (n & 4095);

    float v1[16], v2[16];
    float sa = 0.f, sb = 0.f, dt = 0.f;
#pragma unroll
    for (int j = 0; j < 16; j++) {
        int c = q * 16 + j;
        float a = z1[base + c * 4096];
        float b = z2[base + c * 4096];
        v1[j] = a; v2[j] = b;
        sa = fmaf(a, a, sa);
        sb = fmaf(b, b, sb);
        dt = fmaf(a, b, dt);
    }
    // reduce across the 4 lanes of this row (consecutive lanes)
#pragma unroll
    for (int off = 1; off <= 2; off <<= 1) {
        sa += __shfl_xor_sync(0xffffffffu, sa, off);
        sb += __shfl_xor_sync(0xffffffffu, sb, off);
        dt += __shfl_xor_sync(0xffffffffu, dt, off);
    }
    float inva = 1.f / fmaxf(sqrtf(sa), 1e-12f);
    float invb = 1.f / fmaxf(sqrtf(sb), 1e-12f);

#pragma unroll
    for (int j4 = 0; j4 < 4; j4++) {
        float4 o1, o2;
        o1.x = to_tf32(v1[j4 * 4 + 0] * inva); o1.y = to_tf32(v1[j4 * 4 + 1] * inva);
        o1.z = to_tf32(v1[j4 * 4 + 2] * inva); o1.w = to_tf32(v1[j4 * 4 + 3] * inva);
        o2.x = to_tf32(v2[j4 * 4 + 0] * invb); o2.y = to_tf32(v2[j4 * 4 + 1] * invb);
        o2.z = to_tf32(v2[j4 * 4 + 2] * invb); o2.w = to_tf32(v2[j4 * 4 + 3] * invb);
        int off = n * DDIM + q * 16 + j4 * 4;
        *reinterpret_cast<float4*>(g_z1r + off) = o1;
        *reinterpret_cast<float4*>(g_z2r + off) = o2;
    }
    if (q == 0) g_diag[n] = dt * inva * invb * 10.0f;
}

// ---------------------------------------------------------------------------
// Kernel 2: tf32 HMMA GEMM + fused streaming sum(exp(sim)).
// CTA tile: 128(M) x 128(N), K=64 resident. 8 warps: 4 m-positions x 2 n-positions,
// each warp 32x64 via m16n8k8 fragments (2 m-frags x 8 n-frags x 8 k-steps).
// ---------------------------------------------------------------------------
__global__ void __launch_bounds__(256, 2) gemm_lse_kernel() {
    extern __shared__ float smem[];
    float* As = smem;                 // [128][KPAD]
    float* Bs = smem + BM * KPAD;     // [128][KPAD]

    const int tid  = threadIdx.x;
    const int warp = tid >> 5;
    const int lane = tid & 31;
    const int gr   = lane >> 2;       // group row / n-col within fragment
    const int cc   = lane & 3;        // k sub-col within fragment
    const int wm   = warp >> 1;       // 0..3 : m block of 32
    const int wn   = warp & 1;        // 0..1 : n block of 64
    const int mbase = wm * 32;
    const int nbase = wn * 64;

    const int i0    = blockIdx.x * BM;
    const int jbase = blockIdx.y * (NROWS / NSPLIT);

    // Fill A tile [128][64] -> As[128][KPAD], coalesced float4.
#pragma unroll
    for (int it = 0; it < 8; it++) {
        int e4 = tid + it * 256;
        int m  = e4 >> 4;
        int t4 = e4 & 15;
        float4 v = *reinterpret_cast<const float4*>(g_z1r + (i0 + m) * DDIM + t4 * 4);
        *reinterpret_cast<float4*>(As + m * KPAD + t4 * 4) = v;
    }

    float rs[2][2];
    rs[0][0] = rs[0][1] = rs[1][0] = rs[1][1] = 0.f;

    for (int jt = 0; jt < JTILES; jt++) {
        const int j0 = jbase + jt * BN;
        __syncthreads();   // previous Bs readers done (also covers initial As fill)
#pragma unroll
        for (int it = 0; it < 8; it++) {
            int e4 = tid + it * 256;
            int m  = e4 >> 4;
            int t4 = e4 & 15;
            float4 v = *reinterpret_cast<const float4*>(g_z2r + (j0 + m) * DDIM + t4 * 4);
            *reinterpret_cast<float4*>(Bs + m * KPAD + t4 * 4) = v;
        }
        __syncthreads();

        float acc[2][8][4];
#pragma unroll
        for (int mf = 0; mf < 2; mf++)
#pragma unroll
            for (int nf = 0; nf < 8; nf++)
#pragma unroll
                for (int e = 0; e < 4; e++) acc[mf][nf][e] = 0.f;

#pragma unroll
        for (int ks = 0; ks < 8; ks++) {
            const int k0 = ks * 8;
            uint32_t a[2][4];
#pragma unroll
            for (int mf = 0; mf < 2; mf++) {
                int row = mbase + mf * 16 + gr;
                a[mf][0] = __float_as_uint(As[ row      * KPAD + k0 + cc    ]);
                a[mf][1] = __float_as_uint(As[(row + 8) * KPAD + k0 + cc    ]);
                a[mf][2] = __float_as_uint(As[ row      * KPAD + k0 + cc + 4]);
                a[mf][3] = __float_as_uint(As[(row + 8) * KPAD + k0 + cc + 4]);
            }
            uint32_t b[8][2];
#pragma unroll
            for (int nf = 0; nf < 8; nf++) {
                int col = nbase + nf * 8 + gr;
                b[nf][0] = __float_as_uint(Bs[col * KPAD + k0 + cc    ]);
                b[nf][1] = __float_as_uint(Bs[col * KPAD + k0 + cc + 4]);
            }
#pragma unroll
            for (int mf = 0; mf < 2; mf++)
#pragma unroll
                for (int nf = 0; nf < 8; nf++)
                    mma_tf32(acc[mf][nf], a[mf][0], a[mf][1], a[mf][2], a[mf][3],
                             b[nf][0], b[nf][1]);
        }

        // Fused epilogue: exp(10*sim) = ex2(acc * EXP_SCALE); MUFU pipe.
#pragma unroll
        for (int mf = 0; mf < 2; mf++) {
            float s0 = 0.f, s1 = 0.f;
#pragma unroll
            for (int nf = 0; nf < 8; nf++) {
                s0 += ex2(acc[mf][nf][0] * EXP_SCALE)
                    + ex2(acc[mf][nf][1] * EXP_SCALE);
                s1 += ex2(acc[mf][nf][2] * EXP_SCALE)
                    + ex2(acc[mf][nf][3] * EXP_SCALE);
            }
            rs[mf][0] += s0;
            rs[mf][1] += s1;
        }
    }

    // Reduce over the 4 lanes sharing a row (lane%4 = fragment columns).
#pragma unroll
    for (int off = 1; off <= 2; off <<= 1) {
#pragma unroll
        for (int mf = 0; mf < 2; mf++) {
            rs[mf][0] += __shfl_xor_sync(0xffffffffu, rs[mf][0], off);
            rs[mf][1] += __shfl_xor_sync(0xffffffffu, rs[mf][1], off);
        }
    }
    if (cc == 0) {
        // Two warps (wn=0,1) contribute per row: 2-addend atomicAdd is
        // commutative -> deterministic.
#pragma unroll
        for (int mf = 0; mf < 2; mf++) {
            int row = i0 + mbase + mf * 16 + gr;
            atomicAdd(&g_partial[blockIdx.y * NROWS + row],     rs[mf][0]);
            atomicAdd(&g_partial[blockIdx.y * NROWS + row + 8], rs[mf][1]);
        }
    }
}

// ---------------------------------------------------------------------------
// Kernel 3: combine split partials, lse - diag, mean.
// ---------------------------------------------------------------------------
__global__ void loss_kernel(float* __restrict__ out) {
    __shared__ float red[256];
    int tid = threadIdx.x;
    float s = 0.f;
    for (int i = tid; i < NROWS; i += 256) {
        float rsum = g_partial[i] + g_partial[NROWS + i] +
                     g_partial[2 * NROWS + i] + g_partial[3 * NROWS + i];
        s += logf(rsum) - g_diag[i];
    }
    red[tid] = s;
    __syncthreads();
    for (int o = 128; o > 0; o >>= 1) {
        if (tid < o) red[tid] += red[tid + o];
        __syncthreads();
    }
    if (tid == 0) out[0] = red[0] * (1.0f / NROWS);
}

// ---------------------------------------------------------------------------
extern "C" void kernel_launch(void* const* d_in, const int* in_sizes, int n_in,
                              void* d_out, int out_size) {
    const float* z1 = (const float*)d_in[0];
    const float* z2 = (const float*)d_in[1];
    float* out = (float*)d_out;

    prep_kernel<<<NROWS / 64, 256>>>(z1, z2);

    const size_t smem_bytes = (size_t)(2 * BM * KPAD) * sizeof(float);  // ~69.6 KB
    cudaFuncSetAttribute(gemm_lse_kernel,
                         cudaFuncAttributeMaxDynamicSharedMemorySize,
                         (int)smem_bytes);
    dim3 grid(NROWS / BM, NSPLIT);
    gemm_lse_kernel<<<grid, 256, smem_bytes>>>();

    loss_kernel<<<1, 256>>>(out);
}

// round 5
// speedup vs baseline: 4.1568x; 1.6198x over previous
#include <cuda_runtime.h>
#include <cuda_fp16.h>
#include <math.h>
#include <stdint.h>

#define NROWS 8192
#define DDIM  64
#define BM    128
#define BN    128
#define NSPLIT 4
#define JTILES ((NROWS / NSPLIT) / BN)   // 16 j-tiles per CTA
#define KP2   72                          // fp16 row pitch: 64 + 8 pad (144 B)

// exp(sim/T) = 2^(dot * 10/ln2); fold 10/ln2 into z1 at prep time.
#define EXP_SCALE 14.4269504088896f

// ---------------------------------------------------------------------------
// Scratch (allocation-free: __device__ globals)
// ---------------------------------------------------------------------------
__device__ __half g_z1h[NROWS * DDIM];       // z1n * EXP_SCALE, fp16, row-major
__device__ __half g_z2h[NROWS * DDIM];       // z2n, fp16, row-major
__device__ float  g_partial[NSPLIT * NROWS]; // per-split partial row sums of exp
__device__ float  g_diag[NROWS];             // sim_ii / T (fp32-exact)

__device__ __forceinline__ float ex2(float x) {   // MUFU.EX2
    float r;
    asm("ex2.approx.f32 %0, %1;" : "=f"(r) : "f"(x));
    return r;
}

__device__ __forceinline__ void ldsm_x4(uint32_t addr, uint32_t r[4]) {
    asm volatile("ldmatrix.sync.aligned.m8n8.x4.shared.b16 {%0,%1,%2,%3}, [%4];"
                 : "=r"(r[0]), "=r"(r[1]), "=r"(r[2]), "=r"(r[3]) : "r"(addr));
}

__device__ __forceinline__ void mma_f16(float c[4],
                                        const uint32_t a[4],
                                        uint32_t b0, uint32_t b1) {
    asm volatile(
        "mma.sync.aligned.m16n8k16.row.col.f32.f16.f16.f32 "
        "{%0,%1,%2,%3}, {%4,%5,%6,%7}, {%8,%9}, {%0,%1,%2,%3};"
        : "+f"(c[0]), "+f"(c[1]), "+f"(c[2]), "+f"(c[3])
        : "r"(a[0]), "r"(a[1]), "r"(a[2]), "r"(a[3]), "r"(b0), "r"(b1));
}

// ---------------------------------------------------------------------------
// Kernel 1: normalize rows -> fp16 (z1 pre-scaled by EXP_SCALE); diag fp32.
// 8 threads per row (q = tid&7 handles 8 channels), shfl-reduced.
// Also zero-initializes g_partial.
// ---------------------------------------------------------------------------
__global__ void __launch_bounds__(256) prep_kernel(const float* __restrict__ z1,
                                                   const float* __restrict__ z2) {
    const int tid = threadIdx.x;
    const int gid = blockIdx.x * 256 + tid;
    if (gid < NSPLIT * NROWS) g_partial[gid] = 0.f;

    const int r = tid >> 3;
    const int q = tid & 7;
    const int n = blockIdx.x * 32 + r;
    const int base = (n >> 12) * (DDIM * 4096) + (n & 4095);

    float v1[8], v2[8];
    float sa = 0.f, sb = 0.f, dt = 0.f;
#pragma unroll
    for (int j = 0; j < 8; j++) {
        int c = q * 8 + j;
        float a = z1[base + c * 4096];
        float b = z2[base + c * 4096];
        v1[j] = a; v2[j] = b;
        sa = fmaf(a, a, sa);
        sb = fmaf(b, b, sb);
        dt = fmaf(a, b, dt);
    }
#pragma unroll
    for (int off = 1; off <= 4; off <<= 1) {
        sa += __shfl_xor_sync(0xffffffffu, sa, off);
        sb += __shfl_xor_sync(0xffffffffu, sb, off);
        dt += __shfl_xor_sync(0xffffffffu, dt, off);
    }
    float inva = 1.f / fmaxf(sqrtf(sa), 1e-12f);
    float invb = 1.f / fmaxf(sqrtf(sb), 1e-12f);
    float s1 = inva * EXP_SCALE;

    __half h1[8], h2[8];
#pragma unroll
    for (int j = 0; j < 8; j++) {
        h1[j] = __float2half_rn(v1[j] * s1);
        h2[j] = __float2half_rn(v2[j] * invb);
    }
    int off = n * DDIM + q * 8;
    *reinterpret_cast<float4*>(g_z1h + off) = *reinterpret_cast<float4*>(h1);
    *reinterpret_cast<float4*>(g_z2h + off) = *reinterpret_cast<float4*>(h2);

    if (q == 0) g_diag[n] = dt * inva * invb * 10.0f;
}

// ---------------------------------------------------------------------------
// Kernel 2: fp16 HMMA GEMM + fused streaming sum(exp).
// CTA tile: 128(M) x 128(N), K=64 resident. 8 warps: 4 m-blocks x 2 n-blocks,
// each warp 32x64 via m16n8k16 (2 m-frags x 8 n-frags x 4 k-steps), ldmatrix
// fragment loads, 144B smem row pitch (conflict-free).
// acc already contains dot * 10/ln2, epilogue is bare ex2().
// ---------------------------------------------------------------------------
__global__ void __launch_bounds__(256, 2) gemm_lse_kernel() {
    extern __shared__ __half smem_h[];
    __half* As = smem_h;                  // [128][KP2]
    __half* Bs = smem_h + BM * KP2;       // [128][KP2]

    const int tid  = threadIdx.x;
    const int warp = tid >> 5;
    const int lane = tid & 31;
    const int gr   = lane >> 2;
    const int cc   = lane & 3;
    const int wm   = warp >> 1;           // 0..3
    const int wn   = warp & 1;            // 0..1
    const int mbase = wm * 32;
    const int nbase = wn * 64;

    const int i0    = blockIdx.x * BM;
    const int jbase = blockIdx.y * (NROWS / NSPLIT);

    // ldmatrix source addressing: row = base + lane%16, k-col = k0 + (lane/16)*8
    const int lrow = lane & 15;
    const int lkc  = (lane >> 4) * 8;
    const uint32_t As_u = (uint32_t)__cvta_generic_to_shared(As);
    const uint32_t Bs_u = (uint32_t)__cvta_generic_to_shared(Bs);

    // Fill A tile [128][64] -> As[128][KP2] (16B chunks, coalesced, no conflicts)
#pragma unroll
    for (int it = 0; it < 4; it++) {
        int e = tid + it * 256;           // 1024 chunks: 128 rows x 8
        int m = e >> 3;
        int c = e & 7;
        *reinterpret_cast<float4*>(As + m * KP2 + c * 8) =
            *reinterpret_cast<const float4*>(g_z1h + (i0 + m) * DDIM + c * 8);
    }

    float rs[2][2];
    rs[0][0] = rs[0][1] = rs[1][0] = rs[1][1] = 0.f;

    for (int jt = 0; jt < JTILES; jt++) {
        const int j0 = jbase + jt * BN;
        __syncthreads();   // previous Bs readers done (also covers initial As fill)
#pragma unroll
        for (int it = 0; it < 4; it++) {
            int e = tid + it * 256;
            int m = e >> 3;
            int c = e & 7;
            *reinterpret_cast<float4*>(Bs + m * KP2 + c * 8) =
                *reinterpret_cast<const float4*>(g_z2h + (j0 + m) * DDIM + c * 8);
        }
        __syncthreads();

        float acc[2][8][4];
#pragma unroll
        for (int mf = 0; mf < 2; mf++)
#pragma unroll
            for (int nf = 0; nf < 8; nf++)
#pragma unroll
                for (int e = 0; e < 4; e++) acc[mf][nf][e] = 0.f;

#pragma unroll
        for (int ks = 0; ks < 4; ks++) {
            const int k0 = ks * 16;
            uint32_t a[2][4];
#pragma unroll
            for (int mf = 0; mf < 2; mf++) {
                uint32_t addr = As_u +
                    ((mbase + mf * 16 + lrow) * KP2 + k0 + lkc) * sizeof(__half);
                ldsm_x4(addr, a[mf]);
            }
            uint32_t b[8][2];
#pragma unroll
            for (int np = 0; np < 4; np++) {
                uint32_t r[4];
                uint32_t addr = Bs_u +
                    ((nbase + np * 16 + lrow) * KP2 + k0 + lkc) * sizeof(__half);
                ldsm_x4(addr, r);
                b[2 * np][0]     = r[0];   // n sub 0-7,  k 0-7
                b[2 * np + 1][0] = r[1];   // n sub 8-15, k 0-7
                b[2 * np][1]     = r[2];   // n sub 0-7,  k 8-15
                b[2 * np + 1][1] = r[3];   // n sub 8-15, k 8-15
            }
#pragma unroll
            for (int mf = 0; mf < 2; mf++)
#pragma unroll
                for (int nf = 0; nf < 8; nf++)
                    mma_f16(acc[mf][nf], a[mf], b[nf][0], b[nf][1]);
        }

        // Fused epilogue: acc = dot * 10/ln2  ->  sum 2^acc (MUFU pipe).
#pragma unroll
        for (int mf = 0; mf < 2; mf++) {
            float s0 = 0.f, s1 = 0.f;
#pragma unroll
            for (int nf = 0; nf < 8; nf++) {
                s0 += ex2(acc[mf][nf][0]) + ex2(acc[mf][nf][1]);
                s1 += ex2(acc[mf][nf][2]) + ex2(acc[mf][nf][3]);
            }
            rs[mf][0] += s0;
            rs[mf][1] += s1;
        }
    }

    // Reduce over the 4 lanes sharing a row.
#pragma unroll
    for (int off = 1; off <= 2; off <<= 1) {
#pragma unroll
        for (int mf = 0; mf < 2; mf++) {
            rs[mf][0] += __shfl_xor_sync(0xffffffffu, rs[mf][0], off);
            rs[mf][1] += __shfl_xor_sync(0xffffffffu, rs[mf][1], off);
        }
    }
    if (cc == 0) {
#pragma unroll
        for (int mf = 0; mf < 2; mf++) {
            int row = i0 + mbase + mf * 16 + gr;
            atomicAdd(&g_partial[blockIdx.y * NROWS + row],     rs[mf][0]);
            atomicAdd(&g_partial[blockIdx.y * NROWS + row + 8], rs[mf][1]);
        }
    }
}

// ---------------------------------------------------------------------------
// Kernel 3: combine split partials, lse - diag, mean.
// log(sum 2^x terms): rsum is sum of exp(sim/T) directly since exponents
// already carried the log2e factor. loss = mean(log(rsum) - diag)
// ---------------------------------------------------------------------------
__global__ void loss_kernel(float* __restrict__ out) {
    __shared__ float red[256];
    int tid = threadIdx.x;
    float s = 0.f;
    for (int i = tid; i < NROWS; i += 256) {
        float rsum = g_partial[i] + g_partial[NROWS + i] +
                     g_partial[2 * NROWS + i] + g_partial[3 * NROWS + i];
        s += logf(rsum) - g_diag[i];
    }
    red[tid] = s;
    __syncthreads();
    for (int o = 128; o > 0; o >>= 1) {
        if (tid < o) red[tid] += red[tid + o];
        __syncthreads();
    }
    if (tid == 0) out[0] = red[0] * (1.0f / NROWS);
}

// ---------------------------------------------------------------------------
extern "C" void kernel_launch(void* const* d_in, const int* in_sizes, int n_in,
                              void* d_out, int out_size) {
    const float* z1 = (const float*)d_in[0];
    const float* z2 = (const float*)d_in[1];
    float* out = (float*)d_out;

    prep_kernel<<<NROWS / 32, 256>>>(z1, z2);

    const size_t smem_bytes = (size_t)(2 * BM * KP2) * sizeof(__half);  // 36 KB
    cudaFuncSetAttribute(gemm_lse_kernel,
                         cudaFuncAttributeMaxDynamicSharedMemorySize,
                         (int)smem_bytes);
    dim3 grid(NROWS / BM, NSPLIT);
    gemm_lse_kernel<<<grid, 256, smem_bytes>>>();

    loss_kernel<<<1, 256>>>(out);
}

// round 6
// speedup vs baseline: 4.7082x; 1.1327x over previous
#include <cuda_runtime.h>
#include <cuda_fp16.h>
#include <math.h>
#include <stdint.h>

#define NROWS 8192
#define DDIM  64
#define BM    128
#define BN    128
#define NSPLIT 4
#define JTILES ((NROWS / NSPLIT) / BN)   // 16 j-tiles per CTA
#define KP2   72                          // fp16 row pitch: 64 + 8 pad (144 B)

// exp(sim/T) = 2^(dot * 10/ln2); fold 10/ln2 into z1 at prep time.
#define EXP_SCALE 14.4269504088896f
// accumulators start at -SHIFT so exp2 stays well inside fp16 range
#define SHIFT_LN2 3.4657359028f           // 5 * ln(2)
#define ACC_INIT  0xC500C500u             // half2(-5.0, -5.0)

// ---------------------------------------------------------------------------
// Scratch (allocation-free: __device__ globals)
// ---------------------------------------------------------------------------
__device__ __half g_z1h[NROWS * DDIM];       // z1n * EXP_SCALE, fp16, row-major
__device__ __half g_z2h[NROWS * DDIM];       // z2n, fp16, row-major
__device__ float  g_partial[NSPLIT * NROWS]; // per-split partial row sums of exp*2^-5
__device__ float  g_diag[NROWS];             // sim_ii / T (fp32-exact)

__device__ __forceinline__ __half2 ex2h2(uint32_t x) {   // MUFU, 2 elems/op
    uint32_t r;
    asm("ex2.approx.f16x2 %0, %1;" : "=r"(r) : "r"(x));
    return *reinterpret_cast<__half2*>(&r);
}

__device__ __forceinline__ void ldsm_x4(uint32_t addr, uint32_t r[4]) {
    asm volatile("ldmatrix.sync.aligned.m8n8.x4.shared.b16 {%0,%1,%2,%3}, [%4];"
                 : "=r"(r[0]), "=r"(r[1]), "=r"(r[2]), "=r"(r[3]) : "r"(addr));
}

// fp16-accumulate HMMA: D,C are 2x b32 (half2 pairs)
__device__ __forceinline__ void mma_f16acc(uint32_t c[2],
                                           const uint32_t a[4],
                                           uint32_t b0, uint32_t b1) {
    asm volatile(
        "mma.sync.aligned.m16n8k16.row.col.f16.f16.f16.f16 "
        "{%0,%1}, {%2,%3,%4,%5}, {%6,%7}, {%0,%1};"
        : "+r"(c[0]), "+r"(c[1])
        : "r"(a[0]), "r"(a[1]), "r"(a[2]), "r"(a[3]), "r"(b0), "r"(b1));
}

// ---------------------------------------------------------------------------
// Kernel 1: normalize rows -> fp16 (z1 pre-scaled by EXP_SCALE); diag fp32.
// 8 threads per row, shfl-reduced. Also zero-initializes g_partial.
// ---------------------------------------------------------------------------
__global__ void __launch_bounds__(256) prep_kernel(const float* __restrict__ z1,
                                                   const float* __restrict__ z2) {
    const int tid = threadIdx.x;
    const int gid = blockIdx.x * 256 + tid;
    if (gid < NSPLIT * NROWS) g_partial[gid] = 0.f;

    const int r = tid >> 3;
    const int q = tid & 7;
    const int n = blockIdx.x * 32 + r;
    const int base = (n >> 12) * (DDIM * 4096) + (n & 4095);

    float v1[8], v2[8];
    float sa = 0.f, sb = 0.f, dt = 0.f;
#pragma unroll
    for (int j = 0; j < 8; j++) {
        int c = q * 8 + j;
        float a = z1[base + c * 4096];
        float b = z2[base + c * 4096];
        v1[j] = a; v2[j] = b;
        sa = fmaf(a, a, sa);
        sb = fmaf(b, b, sb);
        dt = fmaf(a, b, dt);
    }
#pragma unroll
    for (int off = 1; off <= 4; off <<= 1) {
        sa += __shfl_xor_sync(0xffffffffu, sa, off);
        sb += __shfl_xor_sync(0xffffffffu, sb, off);
        dt += __shfl_xor_sync(0xffffffffu, dt, off);
    }
    float inva = 1.f / fmaxf(sqrtf(sa), 1e-12f);
    float invb = 1.f / fmaxf(sqrtf(sb), 1e-12f);
    float s1 = inva * EXP_SCALE;

    __half h1[8], h2[8];
#pragma unroll
    for (int j = 0; j < 8; j++) {
        h1[j] = __float2half_rn(v1[j] * s1);
        h2[j] = __float2half_rn(v2[j] * invb);
    }
    int off = n * DDIM + q * 8;
    *reinterpret_cast<float4*>(g_z1h + off) = *reinterpret_cast<float4*>(h1);
    *reinterpret_cast<float4*>(g_z2h + off) = *reinterpret_cast<float4*>(h2);

    if (q == 0) g_diag[n] = dt * inva * invb * 10.0f;
}

// ---------------------------------------------------------------------------
// Kernel 2: fp16-accum HMMA GEMM + fused sum(2^acc).
// CTA: 128x128 tile, K=64 resident, 8 warps (4 m-blocks x 2 n-blocks),
// m16n8k16 fp16 accum. Accumulators initialized to -5.0 so the f16x2 exp2
// stays in range; epilogue = ex2.f16x2 + HADD2 tree, fp32 row accumulation.
// ---------------------------------------------------------------------------
__global__ void __launch_bounds__(256, 2) gemm_lse_kernel() {
    extern __shared__ __half smem_h[];
    __half* As = smem_h;                  // [128][KP2]
    __half* Bs = smem_h + BM * KP2;       // [128][KP2]

    const int tid  = threadIdx.x;
    const int warp = tid >> 5;
    const int lane = tid & 31;
    const int gr   = lane >> 2;
    const int cc   = lane & 3;
    const int wm   = warp >> 1;           // 0..3
    const int wn   = warp & 1;            // 0..1
    const int mbase = wm * 32;
    const int nbase = wn * 64;

    const int i0    = blockIdx.x * BM;
    const int jbase = blockIdx.y * (NROWS / NSPLIT);

    const int lrow = lane & 15;
    const int lkc  = (lane >> 4) * 8;
    const uint32_t As_u = (uint32_t)__cvta_generic_to_shared(As);
    const uint32_t Bs_u = (uint32_t)__cvta_generic_to_shared(Bs);

    // Fill A tile [128][64] -> As[128][KP2]
#pragma unroll
    for (int it = 0; it < 4; it++) {
        int e = tid + it * 256;
        int m = e >> 3;
        int c = e & 7;
        *reinterpret_cast<float4*>(As + m * KP2 + c * 8) =
            *reinterpret_cast<const float4*>(g_z1h + (i0 + m) * DDIM + c * 8);
    }

    float rs[2][2];
    rs[0][0] = rs[0][1] = rs[1][0] = rs[1][1] = 0.f;

    for (int jt = 0; jt < JTILES; jt++) {
        const int j0 = jbase + jt * BN;
        __syncthreads();
#pragma unroll
        for (int it = 0; it < 4; it++) {
            int e = tid + it * 256;
            int m = e >> 3;
            int c = e & 7;
            *reinterpret_cast<float4*>(Bs + m * KP2 + c * 8) =
                *reinterpret_cast<const float4*>(g_z2h + (j0 + m) * DDIM + c * 8);
        }
        __syncthreads();

        // acc[mf][nf][r2]: half2 (two adjacent cols), r2=0 -> row gr, r2=1 -> row gr+8
        uint32_t acc[2][8][2];
#pragma unroll
        for (int mf = 0; mf < 2; mf++)
#pragma unroll
            for (int nf = 0; nf < 8; nf++) {
                acc[mf][nf][0] = ACC_INIT;
                acc[mf][nf][1] = ACC_INIT;
            }

#pragma unroll
        for (int ks = 0; ks < 4; ks++) {
            const int k0 = ks * 16;
            uint32_t a[2][4];
#pragma unroll
            for (int mf = 0; mf < 2; mf++) {
                uint32_t addr = As_u +
                    ((mbase + mf * 16 + lrow) * KP2 + k0 + lkc) * sizeof(__half);
                ldsm_x4(addr, a[mf]);
            }
            uint32_t b[8][2];
#pragma unroll
            for (int np = 0; np < 4; np++) {
                uint32_t r[4];
                uint32_t addr = Bs_u +
                    ((nbase + np * 16 + lrow) * KP2 + k0 + lkc) * sizeof(__half);
                ldsm_x4(addr, r);
                b[2 * np][0]     = r[0];
                b[2 * np + 1][0] = r[1];
                b[2 * np][1]     = r[2];
                b[2 * np + 1][1] = r[3];
            }
#pragma unroll
            for (int mf = 0; mf < 2; mf++)
#pragma unroll
                for (int nf = 0; nf < 8; nf++)
                    mma_f16acc(acc[mf][nf], a[mf], b[nf][0], b[nf][1]);
        }

        // Epilogue: acc = dot*10/ln2 - 5. sum 2^acc via f16x2 ex2 + HADD2 tree.
        // Max elem 2^9.43 ~ 690; 8-wide tree max ~5.5e3 << 65504 (no overflow).
#pragma unroll
        for (int mf = 0; mf < 2; mf++) {
#pragma unroll
            for (int r2 = 0; r2 < 2; r2++) {
                __half2 e0 = ex2h2(acc[mf][0][r2]);
                __half2 e1 = ex2h2(acc[mf][1][r2]);
                __half2 e2 = ex2h2(acc[mf][2][r2]);
                __half2 e3 = ex2h2(acc[mf][3][r2]);
                __half2 e4 = ex2h2(acc[mf][4][r2]);
                __half2 e5 = ex2h2(acc[mf][5][r2]);
                __half2 e6 = ex2h2(acc[mf][6][r2]);
                __half2 e7 = ex2h2(acc[mf][7][r2]);
                e0 = __hadd2(e0, e1);
                e2 = __hadd2(e2, e3);
                e4 = __hadd2(e4, e5);
                e6 = __hadd2(e6, e7);
                e0 = __hadd2(e0, e2);
                e4 = __hadd2(e4, e6);
                e0 = __hadd2(e0, e4);
                float2 f = __half22float2(e0);
                rs[mf][r2] += f.x + f.y;
            }
        }
    }

    // Reduce over the 4 lanes (cc) sharing a row.
#pragma unroll
    for (int off = 1; off <= 2; off <<= 1) {
#pragma unroll
        for (int mf = 0; mf < 2; mf++) {
            rs[mf][0] += __shfl_xor_sync(0xffffffffu, rs[mf][0], off);
            rs[mf][1] += __shfl_xor_sync(0xffffffffu, rs[mf][1], off);
        }
    }
    if (cc == 0) {
#pragma unroll
        for (int mf = 0; mf < 2; mf++) {
            int row = i0 + mbase + mf * 16 + gr;
            atomicAdd(&g_partial[blockIdx.y * NROWS + row],     rs[mf][0]);
            atomicAdd(&g_partial[blockIdx.y * NROWS + row + 8], rs[mf][1]);
        }
    }
}

// ---------------------------------------------------------------------------
// Kernel 3: combine split partials; lse = log(rsum) + 5*ln2; mean(lse - diag).
// ---------------------------------------------------------------------------
__global__ void __launch_bounds__(1024) loss_kernel(float* __restrict__ out) {
    __shared__ float red[1024];
    int tid = threadIdx.x;
    float s = 0.f;
    for (int i = tid; i < NROWS; i += 1024) {
        float rsum = g_partial[i] + g_partial[NROWS + i] +
                     g_partial[2 * NROWS + i] + g_partial[3 * NROWS + i];
        s += logf(rsum) + SHIFT_LN2 - g_diag[i];
    }
    red[tid] = s;
    __syncthreads();
    for (int o = 512; o > 0; o >>= 1) {
        if (tid < o) red[tid] += red[tid + o];
        __syncthreads();
    }
    if (tid == 0) out[0] = red[0] * (1.0f / NROWS);
}

// ---------------------------------------------------------------------------
extern "C" void kernel_launch(void* const* d_in, const int* in_sizes, int n_in,
                              void* d_out, int out_size) {
    const float* z1 = (const float*)d_in[0];
    const float* z2 = (const float*)d_in[1];
    float* out = (float*)d_out;

    prep_kernel<<<NROWS / 32, 256>>>(z1, z2);

    const size_t smem_bytes = (size_t)(2 * BM * KP2) * sizeof(__half);  // 36 KB
    cudaFuncSetAttribute(gemm_lse_kernel,
                         cudaFuncAttributeMaxDynamicSharedMemorySize,
                         (int)smem_bytes);
    dim3 grid(NROWS / BM, NSPLIT);
    gemm_lse_kernel<<<grid, 256, smem_bytes>>>();

    loss_kernel<<<1, 1024>>>(out);
}

// round 8
// speedup vs baseline: 5.4028x; 1.1475x over previous
#include <cuda_runtime.h>
#include <cuda_fp16.h>
#include <math.h>
#include <stdint.h>

#define NROWS 8192
#define DDIM  64
#define TM    128
#define TN    128
#define NSPLIT 16
#define JT    (NROWS / NSPLIT / TN)     // 4 j-tiles per CTA
#define PITCH 80                         // int8 row pitch (64 + 16 pad), 16B-aligned

#define EXP_SCALE 14.4269504088896f     // 10 / ln2
#define SHIFT_LN2 3.4657359028f         // 5 * ln2 (exponent shift compensation)

// ---------------------------------------------------------------------------
// Scratch (allocation-free: __device__ globals)
// ---------------------------------------------------------------------------
__device__ uint32_t g_q1[NROWS * 16];        // z1n quantized s8x4, row-major
__device__ uint32_t g_q2[NROWS * 16];        // z2n quantized s8x4, row-major
__device__ float g_partial[NSPLIT * NROWS];  // per-split row sums of 2^(..)
__device__ float g_diag[NROWS];              // sim_ii / T (fp32-exact)

// ---------------------------------------------------------------------------
// PTX helpers
// ---------------------------------------------------------------------------
__device__ __forceinline__ __half2 ex2h2(uint32_t x) {
    uint32_t r;
    asm("ex2.approx.f16x2 %0, %1;" : "=r"(r) : "r"(x));
    return *reinterpret_cast<__half2*>(&r);
}

__device__ __forceinline__ void ldsm_x4(uint32_t addr, uint32_t r[4]) {
    asm volatile("ldmatrix.sync.aligned.m8n8.x4.shared.b16 {%0,%1,%2,%3}, [%4];"
                 : "=r"(r[0]), "=r"(r[1]), "=r"(r[2]), "=r"(r[3]) : "r"(addr));
}

// int8 IMMA, s32 exact accumulation
__device__ __forceinline__ void mma_s8(uint32_t c[4], const uint32_t a[4],
                                       uint32_t b0, uint32_t b1) {
    asm volatile(
        "mma.sync.aligned.m16n8k32.row.col.s32.s8.s8.s32 "
        "{%0,%1,%2,%3}, {%4,%5,%6,%7}, {%8,%9}, {%0,%1,%2,%3};"
        : "+r"(c[0]), "+r"(c[1]), "+r"(c[2]), "+r"(c[3])
        : "r"(a[0]), "r"(a[1]), "r"(a[2]), "r"(a[3]), "r"(b0), "r"(b1));
}

__device__ __forceinline__ void cp16(uint32_t dst_smem, const void* src) {
    asm volatile("cp.async.cg.shared.global [%0], [%1], 16;"
                 :: "r"(dst_smem), "l"(src) : "memory");
}
#define CP_COMMIT()  asm volatile("cp.async.commit_group;" ::: "memory")
#define CP_WAIT(n)   asm volatile("cp.async.wait_group %0;" :: "n"(n) : "memory")

// exact s32->f32 for |v| < 2^22 via exponent-pinning, fused with scale+shift:
// returns v * kq - 5  (single FFMA rounding)
__device__ __forceinline__ float s32_exp_arg(uint32_t v, float kq, float c0) {
    uint32_t u = v + 0x4B400000u;       // float(2^23*1.5 + v), exact
    return fmaf(__uint_as_float(u), kq, c0);
}

// ---------------------------------------------------------------------------
// Kernel 1: normalize rows -> s8 (scale 127); diag fp32-exact.
// 16 threads per row (4 channels each), shfl-reduced. Zero-inits g_partial.
// ---------------------------------------------------------------------------
__global__ void __launch_bounds__(256) prep_kernel(const float* __restrict__ z1,
                                                   const float* __restrict__ z2) {
    const int tid = threadIdx.x;
    const int gid = blockIdx.x * 256 + tid;
    g_partial[gid] = 0.f;                // 512*256 == NSPLIT*NROWS exactly

    const int r = tid >> 4;
    const int q = tid & 15;
    const int n = blockIdx.x * 16 + r;
    const int base = (n >> 12) * (DDIM * 4096) + (n & 4095);

    float v1[4], v2[4];
    float sa = 0.f, sb = 0.f, dt = 0.f;
#pragma unroll
    for (int j = 0; j < 4; j++) {
        int c = q * 4 + j;
        float a = z1[base + c * 4096];
        float b = z2[base + c * 4096];
        v1[j] = a; v2[j] = b;
        sa = fmaf(a, a, sa);
        sb = fmaf(b, b, sb);
        dt = fmaf(a, b, dt);
    }
#pragma unroll
    for (int off = 1; off <= 8; off <<= 1) {
        sa += __shfl_xor_sync(0xffffffffu, sa, off);
        sb += __shfl_xor_sync(0xffffffffu, sb, off);
        dt += __shfl_xor_sync(0xffffffffu, dt, off);
    }
    float inva = 1.f / fmaxf(sqrtf(sa), 1e-12f);
    float invb = 1.f / fmaxf(sqrtf(sb), 1e-12f);
    float sc1 = inva * 127.f;
    float sc2 = invb * 127.f;

    uint32_t p1 = 0, p2 = 0;
#pragma unroll
    for (int j = 0; j < 4; j++) {
        int s1 = __float2int_rn(v1[j] * sc1);   // |x|<=1 -> [-127,127]
        int s2 = __float2int_rn(v2[j] * sc2);
        p1 |= ((uint32_t)s1 & 0xFFu) << (8 * j);
        p2 |= ((uint32_t)s2 & 0xFFu) << (8 * j);
    }
    g_q1[n * 16 + q] = p1;
    g_q2[n * 16 + q] = p2;

    if (q == 0) g_diag[n] = dt * inva * invb * 10.0f;
}

// ---------------------------------------------------------------------------
// Kernel 2: int8 IMMA GEMM + fused sum(2^(q*kq - 5)).
// CTA: 128x128 tile, K=64 (2 k32 steps). 8 warps = 4 wm x 2 wn, warp 32x64.
// A fragments hoisted (CTA-constant); B double-buffered via cp.async.
// Epilogue: s32 -> f32 (magic add + FFMA, no I2F) -> f16x2 -> ex2 -> hadd2.
// ---------------------------------------------------------------------------
__global__ void __launch_bounds__(256, 2) gemm_lse_kernel() {
    extern __shared__ char smem[];
    const uint32_t sbase = (uint32_t)__cvta_generic_to_shared(smem);
    const uint32_t As  = sbase;                 // 128 * 80 = 10240 B
    const uint32_t Bs0 = sbase + 10240;
    const uint32_t Bs1 = sbase + 20480;

    const int tid  = threadIdx.x;
    const int warp = tid >> 5;
    const int lane = tid & 31;
    const int gr   = lane >> 2;
    const int cc   = lane & 3;
    const int wm   = warp >> 1;
    const int wn   = warp & 1;
    const int mbase = wm * 32;
    const int nbase = wn * 64;
    const int lrow = lane & 15;
    const int lk16 = (lane >> 4) * 16;          // byte column for ldmatrix

    const int i0    = blockIdx.x * TM;
    const int jbase = blockIdx.y * (NROWS / NSPLIT);

    const float KQ = EXP_SCALE / 16129.f;       // 10/ln2 / 127^2
    const float C0 = -12582912.f * KQ - 5.f;

    // Prologue: A tile + B tile 0 via cp.async (2+2 chunks of 16B per thread)
#pragma unroll
    for (int it = 0; it < 2; it++) {
        int e = tid + it * 256;                  // 512 chunks: 128 rows x 4
        int m = e >> 2;
        int c = e & 3;
        cp16(As  + m * PITCH + c * 16, g_q1 + (i0 + m) * 16 + c * 4);
        cp16(Bs0 + m * PITCH + c * 16, g_q2 + (jbase + m) * 16 + c * 4);
    }
    CP_COMMIT();
    CP_WAIT(0);
    __syncthreads();

    // Hoist A fragments: a[ks][mf][4]
    uint32_t a[2][2][4];
#pragma unroll
    for (int ks = 0; ks < 2; ks++)
#pragma unroll
        for (int mf = 0; mf < 2; mf++)
            ldsm_x4(As + (mbase + mf * 16 + lrow) * PITCH + lk16 + ks * 32,
                    a[ks][mf]);

    float rs[2][2];
    rs[0][0] = rs[0][1] = rs[1][0] = rs[1][1] = 0.f;

    for (int t = 0; t < JT; t++) {
        const uint32_t Bcur = (t & 1) ? Bs1 : Bs0;
        __syncthreads();                         // everyone done with buf(t-1)
        if (t + 1 < JT) {
            const uint32_t Bnxt = (t & 1) ? Bs0 : Bs1;
            const int j0 = jbase + (t + 1) * TN;
#pragma unroll
            for (int it = 0; it < 2; it++) {
                int e = tid + it * 256;
                int m = e >> 2;
                int c = e & 3;
                cp16(Bnxt + m * PITCH + c * 16, g_q2 + (j0 + m) * 16 + c * 4);
            }
            CP_COMMIT();
            CP_WAIT(1);                          // B[t] done; B[t+1] in flight
        } else {
            CP_WAIT(0);
        }
        __syncthreads();

        // Two n-halves of 32 cols each to cap live registers
#pragma unroll
        for (int nh = 0; nh < 2; nh++) {
            uint32_t acc[2][4][4];
#pragma unroll
            for (int mf = 0; mf < 2; mf++)
#pragma unroll
                for (int nf = 0; nf < 4; nf++)
#pragma unroll
                    for (int e = 0; e < 4; e++) acc[mf][nf][e] = 0u;

#pragma unroll
            for (int ks = 0; ks < 2; ks++) {
                uint32_t b[4][2];
#pragma unroll
                for (int np = 0; np < 2; np++) {
                    uint32_t r[4];
                    ldsm_x4(Bcur + (nbase + nh * 32 + np * 16 + lrow) * PITCH +
                                lk16 + ks * 32, r);
                    b[2 * np][0]     = r[0];
                    b[2 * np + 1][0] = r[1];
                    b[2 * np][1]     = r[2];
                    b[2 * np + 1][1] = r[3];
                }
#pragma unroll
                for (int mf = 0; mf < 2; mf++)
#pragma unroll
                    for (int nf = 0; nf < 4; nf++)
                        mma_s8(acc[mf][nf], a[ks][mf], b[nf][0], b[nf][1]);
            }

            // Epilogue: v*KQ - 5 -> f16x2 -> ex2 -> hadd2 tree -> fp32 rows
#pragma unroll
            for (int mf = 0; mf < 2; mf++) {
#pragma unroll
                for (int r2 = 0; r2 < 2; r2++) {
                    __half2 hs = __floats2half2_rn(0.f, 0.f);
#pragma unroll
                    for (int nf = 0; nf < 4; nf++) {
                        float f0 = s32_exp_arg(acc[mf][nf][2 * r2],     KQ, C0);
                        float f1 = s32_exp_arg(acc[mf][nf][2 * r2 + 1], KQ, C0);
                        uint32_t h;
                        asm("cvt.rn.f16x2.f32 %0, %1, %2;" : "=r"(h)
                            : "f"(f1), "f"(f0));
                        hs = __hadd2(hs, ex2h2(h));
                    }
                    float2 fr = __half22float2(hs);
                    rs[mf][r2] += fr.x + fr.y;
                }
            }
        }
    }

    // Reduce over the 4 lanes (cc) sharing a row.
#pragma unroll
    for (int off = 1; off <= 2; off <<= 1) {
#pragma unroll
        for (int mf = 0; mf < 2; mf++) {
            rs[mf][0] += __shfl_xor_sync(0xffffffffu, rs[mf][0], off);
            rs[mf][1] += __shfl_xor_sync(0xffffffffu, rs[mf][1], off);
        }
    }
    if (cc == 0) {
        // Two warps (wn=0/1) per row: 2-addend atomicAdd, commutative ->
        // deterministic.
#pragma unroll
        for (int mf = 0; mf < 2; mf++) {
            int row = i0 + mbase + mf * 16 + gr;
            atomicAdd(&g_partial[blockIdx.y * NROWS + row],     rs[mf][0]);
            atomicAdd(&g_partial[blockIdx.y * NROWS + row + 8], rs[mf][1]);
        }
    }
}

// ---------------------------------------------------------------------------
// Kernel 3: combine split partials; lse = log(rsum) + 5*ln2; mean(lse - diag).
// ---------------------------------------------------------------------------
__global__ void __launch_bounds__(1024) loss_kernel(float* __restrict__ out) {
    __shared__ float red[1024];
    int tid = threadIdx.x;
    float s = 0.f;
    for (int i = tid; i < NROWS; i += 1024) {
        float rsum = 0.f;
#pragma unroll
        for (int p = 0; p < NSPLIT; p++) rsum += g_partial[p * NROWS + i];
        s += logf(rsum) + SHIFT_LN2 - g_diag[i];
    }
    red[tid] = s;
    __syncthreads();
    for (int o = 512; o > 0; o >>= 1) {
        if (tid < o) red[tid] += red[tid + o];
        __syncthreads();
    }
    if (tid == 0) out[0] = red[0] * (1.0f / NROWS);
}

// ---------------------------------------------------------------------------
extern "C" void kernel_launch(void* const* d_in, const int* in_sizes, int n_in,
                              void* d_out, int out_size) {
    const float* z1 = (const float*)d_in[0];
    const float* z2 = (const float*)d_in[1];
    float* out = (float*)d_out;

    prep_kernel<<<NROWS / 16, 256>>>(z1, z2);

    const size_t smem_bytes = 3 * TM * PITCH;   // 30720 B
    dim3 grid(NROWS / TM, NSPLIT);
    gemm_lse_kernel<<<grid, 256, smem_bytes>>>();

    loss_kernel<<<1, 1024>>>(out);
}